// round 1
// baseline (speedup 1.0000x reference)
#include <cuda_runtime.h>
#include <cuda_bf16.h>
#include <math.h>

// ---------------- Problem constants ----------------
#define B_  64
#define S_  256
#define H_  768
#define L_  12
#define NH_ 12
#define HD_ 64
#define FF_ 3072
#define NTOK (B_ * S_)          // 16384
#define NL_ 2

// ---------------- Scratch (static device globals; no allocation) ----------------
__device__ float g_h  [NTOK * H_];
__device__ float g_q  [NTOK * H_];
__device__ float g_k  [NTOK * H_];
__device__ float g_v  [NTOK * H_];
__device__ float g_ctx[NTOK * H_];
__device__ float g_tmp[NTOK * H_];
__device__ float g_ffn[(size_t)NTOK * FF_];

// ---------------- Block reduction helper ----------------
__device__ __forceinline__ float block_sum(float v, float* red) {
    #pragma unroll
    for (int o = 16; o; o >>= 1) v += __shfl_xor_sync(0xffffffffu, v, o);
    int w = threadIdx.x >> 5, l = threadIdx.x & 31;
    if (l == 0) red[w] = v;
    __syncthreads();
    if (w == 0) {
        v = (l < (int)(blockDim.x >> 5)) ? red[l] : 0.0f;
        #pragma unroll
        for (int o = 16; o; o >>= 1) v += __shfl_xor_sync(0xffffffffu, v, o);
        if (l == 0) red[0] = v;
    }
    __syncthreads();
    float r = red[0];
    __syncthreads();   // allow reuse of red
    return r;
}

// ---------------- Embedding + LayerNorm (one block per token) ----------------
__global__ void embed_ln_kernel(const int* __restrict__ ids,
                                const int* __restrict__ tt,
                                const float* __restrict__ we,
                                const float* __restrict__ pe,
                                const float* __restrict__ te,
                                const float* __restrict__ s,
                                const float* __restrict__ b,
                                float* __restrict__ out) {
    __shared__ float red[32];
    int tok = blockIdx.x;
    int tid = threadIdx.x;
    int srow = tok % S_;
    int id = ids[tok];
    int t  = tt[tok];
    float x[3];
    #pragma unroll
    for (int r = 0; r < 3; r++) {
        int i = tid + 256 * r;
        x[r] = we[(size_t)id * H_ + i] + pe[(size_t)srow * H_ + i] + te[(size_t)t * H_ + i];
    }
    float sum = block_sum(x[0] + x[1] + x[2], red);
    float m = sum * (1.0f / H_);
    float vs = 0.0f;
    #pragma unroll
    for (int r = 0; r < 3; r++) { float d = x[r] - m; vs += d * d; }
    vs = block_sum(vs, red);
    float inv = rsqrtf(vs * (1.0f / H_) + 1e-12f);
    #pragma unroll
    for (int r = 0; r < 3; r++) {
        int i = tid + 256 * r;
        out[(size_t)tok * H_ + i] = (x[r] - m) * inv * s[i] + b[i];
    }
}

// ---------------- Residual add + LayerNorm (in place on h) ----------------
__global__ void add_ln_kernel(float* __restrict__ h,
                              const float* __restrict__ t,
                              const float* __restrict__ s,
                              const float* __restrict__ b) {
    __shared__ float red[32];
    int tok = blockIdx.x;
    int tid = threadIdx.x;
    float x[3];
    #pragma unroll
    for (int r = 0; r < 3; r++) {
        int i = tid + 256 * r;
        x[r] = h[(size_t)tok * H_ + i] + t[(size_t)tok * H_ + i];
    }
    float sum = block_sum(x[0] + x[1] + x[2], red);
    float m = sum * (1.0f / H_);
    float vs = 0.0f;
    #pragma unroll
    for (int r = 0; r < 3; r++) { float d = x[r] - m; vs += d * d; }
    vs = block_sum(vs, red);
    float inv = rsqrtf(vs * (1.0f / H_) + 1e-12f);
    #pragma unroll
    for (int r = 0; r < 3; r++) {
        int i = tid + 256 * r;
        h[(size_t)tok * H_ + i] = (x[r] - m) * inv * s[i] + b[i];
    }
}

// ---------------- SGEMM: C[M,N] = A[M,K] @ B[K,N] + bias, optional exact GELU ----------------
// 128x128 tile, BK=8, 256 threads, 8x8 register tile. Dims are multiples of 128/8.
__global__ void gemm_bias_kernel(const float* __restrict__ A,
                                 const float* __restrict__ Bm,
                                 const float* __restrict__ bias,
                                 float* __restrict__ C,
                                 int M, int N, int K, int act) {
    __shared__ float As[8][128];
    __shared__ float Bs[8][128];
    int tid = threadIdx.x;
    int bm = blockIdx.y * 128;
    int bn = blockIdx.x * 128;
    int ty = tid >> 4, tx = tid & 15;

    int a_row = tid >> 1;
    int a_col = (tid & 1) * 4;
    int b_row = tid >> 5;
    int b_col = (tid & 31) * 4;

    const float* Aptr = A  + (size_t)(bm + a_row) * K + a_col;
    const float* Bptr = Bm + (size_t)b_row * N + bn + b_col;

    float acc[8][8];
    #pragma unroll
    for (int i = 0; i < 8; i++)
        #pragma unroll
        for (int j = 0; j < 8; j++) acc[i][j] = 0.0f;

    for (int k0 = 0; k0 < K; k0 += 8) {
        float4 av = *reinterpret_cast<const float4*>(Aptr + k0);
        float4 bv = *reinterpret_cast<const float4*>(Bptr + (size_t)k0 * N);
        As[a_col + 0][a_row] = av.x;
        As[a_col + 1][a_row] = av.y;
        As[a_col + 2][a_row] = av.z;
        As[a_col + 3][a_row] = av.w;
        *reinterpret_cast<float4*>(&Bs[b_row][b_col]) = bv;
        __syncthreads();
        #pragma unroll
        for (int k = 0; k < 8; k++) {
            float af[8], bf[8];
            *(float4*)&af[0] = *(float4*)&As[k][ty * 8];
            *(float4*)&af[4] = *(float4*)&As[k][ty * 8 + 4];
            *(float4*)&bf[0] = *(float4*)&Bs[k][tx * 8];
            *(float4*)&bf[4] = *(float4*)&Bs[k][tx * 8 + 4];
            #pragma unroll
            for (int i = 0; i < 8; i++)
                #pragma unroll
                for (int j = 0; j < 8; j++)
                    acc[i][j] = fmaf(af[i], bf[j], acc[i][j]);
        }
        __syncthreads();
    }

    #pragma unroll
    for (int i = 0; i < 8; i++) {
        int m = bm + ty * 8 + i;
        #pragma unroll
        for (int j = 0; j < 8; j++) {
            int n = bn + tx * 8 + j;
            float vv = acc[i][j] + bias[n];
            if (act == 1) vv = 0.5f * vv * (1.0f + erff(vv * 0.70710678118654752f));
            C[(size_t)m * N + n] = vv;
        }
    }
}

// ---------------- Attention: one block per (b, head); K/V resident in smem ----------------
__global__ void attention_kernel(const float* __restrict__ Q,
                                 const float* __restrict__ K,
                                 const float* __restrict__ V,
                                 const int* __restrict__ mask,
                                 float* __restrict__ O) {
    extern __shared__ float sm[];
    float* Ks    = sm;                   // 256 * 68
    float* Vs    = Ks + 256 * 68;        // 256 * 68
    float* qs    = Vs + 256 * 68;        // 8 * 68
    float* biasv = qs + 8 * 68;          // 256
    float* probs = biasv + 256;          // 8 * 256

    int bh = blockIdx.x;
    int b = bh / NH_, h = bh % NH_;
    int tid = threadIdx.x, lane = tid & 31, w = tid >> 5;
    const size_t base = ((size_t)b * S_) * H_ + (size_t)h * HD_;

    for (int idx = tid; idx < 256 * 16; idx += 256) {
        int row = idx >> 4, c4 = idx & 15;
        float4 kv = *(const float4*)(K + base + (size_t)row * H_ + c4 * 4);
        float4 vv = *(const float4*)(V + base + (size_t)row * H_ + c4 * 4);
        *(float4*)(Ks + row * 68 + c4 * 4) = kv;
        *(float4*)(Vs + row * 68 + c4 * 4) = vv;
    }
    biasv[tid] = (1.0f - (float)mask[b * S_ + tid]) * -10000.0f;
    __syncthreads();

    const float scale = 0.125f;  // 1/sqrt(64)
    for (int r = w; r < S_; r += 8) {
        __syncwarp();
        if (lane < 16)
            *(float4*)(qs + w * 68 + lane * 4) =
                *(const float4*)(Q + base + (size_t)r * H_ + lane * 4);
        __syncwarp();

        float sc[8];
        #pragma unroll
        for (int t = 0; t < 8; t++) {
            int j = t * 32 + lane;
            float a = 0.0f;
            #pragma unroll
            for (int d4 = 0; d4 < 16; d4++) {
                float4 kq = *(float4*)(Ks + j * 68 + d4 * 4);
                float4 qq = *(float4*)(qs + w * 68 + d4 * 4);
                a = fmaf(kq.x, qq.x, fmaf(kq.y, qq.y, fmaf(kq.z, qq.z, fmaf(kq.w, qq.w, a))));
            }
            sc[t] = a * scale + biasv[j];
        }
        float mx = sc[0];
        #pragma unroll
        for (int t = 1; t < 8; t++) mx = fmaxf(mx, sc[t]);
        #pragma unroll
        for (int o = 16; o; o >>= 1) mx = fmaxf(mx, __shfl_xor_sync(0xffffffffu, mx, o));
        float sum = 0.0f;
        #pragma unroll
        for (int t = 0; t < 8; t++) { sc[t] = __expf(sc[t] - mx); sum += sc[t]; }
        #pragma unroll
        for (int o = 16; o; o >>= 1) sum += __shfl_xor_sync(0xffffffffu, sum, o);
        float inv = 1.0f / sum;
        #pragma unroll
        for (int t = 0; t < 8; t++) probs[w * 256 + t * 32 + lane] = sc[t] * inv;
        __syncwarp();

        float a0 = 0.0f, a1 = 0.0f;
        for (int j = 0; j < 256; j++) {
            float p = probs[w * 256 + j];
            a0 = fmaf(p, Vs[j * 68 + lane], a0);
            a1 = fmaf(p, Vs[j * 68 + 32 + lane], a1);
        }
        O[base + (size_t)r * H_ + lane]      = a0;
        O[base + (size_t)r * H_ + 32 + lane] = a1;
    }
}

// ---------------- Classification head ----------------
__global__ void head_kernel(const float* __restrict__ h,
                            const int* __restrict__ ann,
                            const float* __restrict__ hw,
                            const float* __restrict__ hb,
                            float* __restrict__ out) {
    __shared__ float red[32];
    int b = blockIdx.x;
    int tid = threadIdx.x;
    int a = ann[b];
    const float* cls = h + (size_t)b * S_ * H_;   // token (b, 0)
    const float* w = hw + (size_t)a * H_ * NL_;
    float a0 = 0.0f, a1 = 0.0f;
    for (int i = tid; i < H_; i += 256) {
        float c = cls[i];
        a0 = fmaf(c, w[i * NL_ + 0], a0);
        a1 = fmaf(c, w[i * NL_ + 1], a1);
    }
    a0 = block_sum(a0, red);
    a1 = block_sum(a1, red);
    if (tid == 0) {
        out[b * NL_ + 0] = a0 + hb[a * NL_ + 0];
        out[b * NL_ + 1] = a1 + hb[a * NL_ + 1];
    }
}

// ---------------- Host launcher ----------------
extern "C" void kernel_launch(void* const* d_in, const int* in_sizes, int n_in,
                              void* d_out, int out_size) {
    (void)in_sizes; (void)n_in; (void)out_size;
    const int*   ids   = (const int*)  d_in[0];
    const int*   amask = (const int*)  d_in[1];
    const int*   tt    = (const int*)  d_in[2];
    const int*   ann   = (const int*)  d_in[3];
    const float* we    = (const float*)d_in[4];
    const float* pe    = (const float*)d_in[5];
    const float* te    = (const float*)d_in[6];
    const float* elns  = (const float*)d_in[7];
    const float* elnb  = (const float*)d_in[8];
    const float* Wq    = (const float*)d_in[9];
    const float* bq    = (const float*)d_in[10];
    const float* Wk    = (const float*)d_in[11];
    const float* bk    = (const float*)d_in[12];
    const float* Wv    = (const float*)d_in[13];
    const float* bv    = (const float*)d_in[14];
    const float* Wo    = (const float*)d_in[15];
    const float* bo    = (const float*)d_in[16];
    const float* l1s   = (const float*)d_in[17];
    const float* l1b   = (const float*)d_in[18];
    const float* W1    = (const float*)d_in[19];
    const float* b1    = (const float*)d_in[20];
    const float* W2    = (const float*)d_in[21];
    const float* b2    = (const float*)d_in[22];
    const float* l2s   = (const float*)d_in[23];
    const float* l2b   = (const float*)d_in[24];
    const float* hw    = (const float*)d_in[25];
    const float* hb    = (const float*)d_in[26];
    float* out = (float*)d_out;

    float *h, *q, *k, *v, *ctx, *tmp, *ffn;
    cudaGetSymbolAddress((void**)&h,   g_h);
    cudaGetSymbolAddress((void**)&q,   g_q);
    cudaGetSymbolAddress((void**)&k,   g_k);
    cudaGetSymbolAddress((void**)&v,   g_v);
    cudaGetSymbolAddress((void**)&ctx, g_ctx);
    cudaGetSymbolAddress((void**)&tmp, g_tmp);
    cudaGetSymbolAddress((void**)&ffn, g_ffn);

    const int asmem = (256 * 68 * 2 + 8 * 68 + 256 + 8 * 256) * 4;
    cudaFuncSetAttribute(attention_kernel,
                         cudaFuncAttributeMaxDynamicSharedMemorySize, asmem);

    embed_ln_kernel<<<NTOK, 256>>>(ids, tt, we, pe, te, elns, elnb, h);

    dim3 gH (H_  / 128, NTOK / 128);   // (6, 128)
    dim3 gFF(FF_ / 128, NTOK / 128);   // (24, 128)

    for (int l = 0; l < L_; l++) {
        const float* wq = Wq + (size_t)l * H_ * H_;
        const float* wk = Wk + (size_t)l * H_ * H_;
        const float* wv = Wv + (size_t)l * H_ * H_;
        const float* wo = Wo + (size_t)l * H_ * H_;
        const float* w1 = W1 + (size_t)l * H_ * FF_;
        const float* w2 = W2 + (size_t)l * FF_ * H_;

        gemm_bias_kernel<<<gH, 256>>>(h, wq, bq + (size_t)l * H_, q, NTOK, H_, H_, 0);
        gemm_bias_kernel<<<gH, 256>>>(h, wk, bk + (size_t)l * H_, k, NTOK, H_, H_, 0);
        gemm_bias_kernel<<<gH, 256>>>(h, wv, bv + (size_t)l * H_, v, NTOK, H_, H_, 0);

        attention_kernel<<<B_ * NH_, 256, asmem>>>(q, k, v, amask, ctx);

        gemm_bias_kernel<<<gH, 256>>>(ctx, wo, bo + (size_t)l * H_, tmp, NTOK, H_, H_, 0);
        add_ln_kernel<<<NTOK, 256>>>(h, tmp, l1s + (size_t)l * H_, l1b + (size_t)l * H_);

        gemm_bias_kernel<<<gFF, 256>>>(h, w1, b1 + (size_t)l * FF_, ffn, NTOK, FF_, H_, 1);
        gemm_bias_kernel<<<gH, 256>>>(ffn, w2, b2 + (size_t)l * H_, tmp, NTOK, H_, FF_, 0);
        add_ln_kernel<<<NTOK, 256>>>(h, tmp, l2s + (size_t)l * H_, l2b + (size_t)l * H_);
    }

    head_kernel<<<B_, 256>>>(h, ann, hw, hb, out);
}

// round 3
// speedup vs baseline: 2.0418x; 2.0418x over previous
#include <cuda_runtime.h>
#include <cuda_bf16.h>
#include <math.h>
#include <cstdint>

// ---------------- Problem constants ----------------
#define B_  64
#define S_  256
#define H_  768
#define L_  12
#define NH_ 12
#define HD_ 64
#define FF_ 3072
#define NTOK (B_ * S_)          // 16384
#define NL_ 2
#define QS_ 2304                // fused qkv row stride

// ---------------- Scratch (static device globals; no allocation) ----------------
__device__ float g_h  [NTOK * H_];
__device__ float g_tmp[NTOK * H_];
__device__ float g_qkv[(size_t)NTOK * QS_];

__device__ __nv_bfloat16 g_hh[NTOK * H_];
__device__ __nv_bfloat16 g_hl[NTOK * H_];
__device__ __nv_bfloat16 g_ch[NTOK * H_];
__device__ __nv_bfloat16 g_cl[NTOK * H_];
__device__ __nv_bfloat16 g_fh[(size_t)NTOK * FF_];
__device__ __nv_bfloat16 g_fl[(size_t)NTOK * FF_];

// transposed + split weights: [L][N][K] (K-major rows)
__device__ __nv_bfloat16 g_Wqkvh[(size_t)L_ * QS_ * H_];
__device__ __nv_bfloat16 g_Wqkvl[(size_t)L_ * QS_ * H_];
__device__ __nv_bfloat16 g_Woh[(size_t)L_ * H_ * H_];
__device__ __nv_bfloat16 g_Wol[(size_t)L_ * H_ * H_];
__device__ __nv_bfloat16 g_W1h[(size_t)L_ * H_ * FF_];
__device__ __nv_bfloat16 g_W1l[(size_t)L_ * H_ * FF_];
__device__ __nv_bfloat16 g_W2h[(size_t)L_ * H_ * FF_];
__device__ __nv_bfloat16 g_W2l[(size_t)L_ * H_ * FF_];
__device__ float g_bqkv[L_ * QS_];

// ---------------- low-level helpers ----------------
__device__ __forceinline__ uint32_t smem_u32(const void* p) {
    uint32_t a;
    asm("{ .reg .u64 t; cvta.to.shared.u64 t, %1; cvt.u32.u64 %0, t; }" : "=r"(a) : "l"(p));
    return a;
}
__device__ __forceinline__ void cp16(uint32_t dst, const void* src) {
    asm volatile("cp.async.cg.shared.global [%0], [%1], 16;" :: "r"(dst), "l"(src) : "memory");
}
__device__ __forceinline__ void cp_commit() { asm volatile("cp.async.commit_group;" ::: "memory"); }
__device__ __forceinline__ void cp_wait0()  { asm volatile("cp.async.wait_group 0;" ::: "memory"); }
__device__ __forceinline__ void cp_wait1()  { asm volatile("cp.async.wait_group 1;" ::: "memory"); }

__device__ __forceinline__ void ldm_x4(uint32_t* r, uint32_t addr) {
    asm volatile("ldmatrix.sync.aligned.m8n8.x4.shared.b16 {%0,%1,%2,%3}, [%4];"
                 : "=r"(r[0]), "=r"(r[1]), "=r"(r[2]), "=r"(r[3]) : "r"(addr));
}
__device__ __forceinline__ void mma16816(float* d, const uint32_t* a, const uint32_t* b) {
    asm volatile("mma.sync.aligned.m16n8k16.row.col.f32.bf16.bf16.f32 "
                 "{%0,%1,%2,%3}, {%4,%5,%6,%7}, {%8,%9}, {%0,%1,%2,%3};"
                 : "+f"(d[0]), "+f"(d[1]), "+f"(d[2]), "+f"(d[3])
                 : "r"(a[0]), "r"(a[1]), "r"(a[2]), "r"(a[3]), "r"(b[0]), "r"(b[1]));
}

__device__ __forceinline__ void split2(float v, __nv_bfloat16& h, __nv_bfloat16& l) {
    h = __float2bfloat16(v);
    l = __float2bfloat16(v - __bfloat162float(h));
}

// ---------------- Block reduction helper ----------------
__device__ __forceinline__ float block_sum(float v, float* red) {
    #pragma unroll
    for (int o = 16; o; o >>= 1) v += __shfl_xor_sync(0xffffffffu, v, o);
    int w = threadIdx.x >> 5, l = threadIdx.x & 31;
    if (l == 0) red[w] = v;
    __syncthreads();
    if (w == 0) {
        v = (l < (int)(blockDim.x >> 5)) ? red[l] : 0.0f;
        #pragma unroll
        for (int o = 16; o; o >>= 1) v += __shfl_xor_sync(0xffffffffu, v, o);
        if (l == 0) red[0] = v;
    }
    __syncthreads();
    float r = red[0];
    __syncthreads();
    return r;
}

// ---------------- Weight prep: W[L][K][N] fp32 -> Wh/Wl [L][Ntot][K] bf16 (row noff..noff+N) ----
__global__ void prep_w_kernel(const float* __restrict__ W,
                              __nv_bfloat16* __restrict__ Wh,
                              __nv_bfloat16* __restrict__ Wl,
                              int K, int N, int Ntot, int noff) {
    __shared__ float t[32][33];
    int l  = blockIdx.z;
    int k0 = blockIdx.y * 32, n0 = blockIdx.x * 32;
    const float* Wp = W + (size_t)l * K * N;
    for (int r = threadIdx.y; r < 32; r += 8)
        t[r][threadIdx.x] = Wp[(size_t)(k0 + r) * N + n0 + threadIdx.x];
    __syncthreads();
    for (int r = threadIdx.y; r < 32; r += 8) {
        int n = n0 + r, k = k0 + threadIdx.x;
        float v = t[threadIdx.x][r];
        __nv_bfloat16 hh, ll;
        split2(v, hh, ll);
        size_t o = (size_t)l * Ntot * K + (size_t)(noff + n) * K + k;
        Wh[o] = hh; Wl[o] = ll;
    }
}

__global__ void concat_bias_kernel(const float* __restrict__ bq,
                                   const float* __restrict__ bk,
                                   const float* __restrict__ bv,
                                   float* __restrict__ dst) {
    int i = blockIdx.x * 256 + threadIdx.x;
    if (i >= L_ * QS_) return;
    int l = i / QS_, n = i % QS_;
    float v = (n < H_) ? bq[l * H_ + n]
            : (n < 2 * H_) ? bk[l * H_ + n - H_]
            : bv[l * H_ + n - 2 * H_];
    dst[i] = v;
}

// ---------------- Embedding + LayerNorm (+ bf16 hi/lo split) ----------------
__global__ void embed_ln_kernel(const int* __restrict__ ids,
                                const int* __restrict__ tt,
                                const float* __restrict__ we,
                                const float* __restrict__ pe,
                                const float* __restrict__ te,
                                const float* __restrict__ s,
                                const float* __restrict__ b,
                                float* __restrict__ out,
                                __nv_bfloat16* __restrict__ oh,
                                __nv_bfloat16* __restrict__ ol) {
    __shared__ float red[32];
    int tok = blockIdx.x;
    int tid = threadIdx.x;
    int srow = tok % S_;
    int id = ids[tok];
    int t  = tt[tok];
    float x[3];
    #pragma unroll
    for (int r = 0; r < 3; r++) {
        int i = tid + 256 * r;
        x[r] = we[(size_t)id * H_ + i] + pe[(size_t)srow * H_ + i] + te[(size_t)t * H_ + i];
    }
    float sum = block_sum(x[0] + x[1] + x[2], red);
    float m = sum * (1.0f / H_);
    float vs = 0.0f;
    #pragma unroll
    for (int r = 0; r < 3; r++) { float d = x[r] - m; vs += d * d; }
    vs = block_sum(vs, red);
    float inv = rsqrtf(vs * (1.0f / H_) + 1e-12f);
    #pragma unroll
    for (int r = 0; r < 3; r++) {
        int i = tid + 256 * r;
        float vv = (x[r] - m) * inv * s[i] + b[i];
        size_t o = (size_t)tok * H_ + i;
        out[o] = vv;
        __nv_bfloat16 hh, ll; split2(vv, hh, ll);
        oh[o] = hh; ol[o] = ll;
    }
}

// ---------------- Residual add + LayerNorm (in place) + bf16 hi/lo ----------------
__global__ void add_ln_kernel(float* __restrict__ h,
                              const float* __restrict__ t,
                              const float* __restrict__ s,
                              const float* __restrict__ b,
                              __nv_bfloat16* __restrict__ oh,
                              __nv_bfloat16* __restrict__ ol) {
    __shared__ float red[32];
    int tok = blockIdx.x;
    int tid = threadIdx.x;
    float x[3];
    #pragma unroll
    for (int r = 0; r < 3; r++) {
        int i = tid + 256 * r;
        x[r] = h[(size_t)tok * H_ + i] + t[(size_t)tok * H_ + i];
    }
    float sum = block_sum(x[0] + x[1] + x[2], red);
    float m = sum * (1.0f / H_);
    float vs = 0.0f;
    #pragma unroll
    for (int r = 0; r < 3; r++) { float d = x[r] - m; vs += d * d; }
    vs = block_sum(vs, red);
    float inv = rsqrtf(vs * (1.0f / H_) + 1e-12f);
    #pragma unroll
    for (int r = 0; r < 3; r++) {
        int i = tid + 256 * r;
        float vv = (x[r] - m) * inv * s[i] + b[i];
        size_t o = (size_t)tok * H_ + i;
        h[o] = vv;
        __nv_bfloat16 hh, ll; split2(vv, hh, ll);
        oh[o] = hh; ol[o] = ll;
    }
}

// ---------------- mma.sync GEMM with bf16x3 fp32 emulation ----------------
// C[M,N] = A[M,K] @ B[N,K]^T + bias ; A,B as bf16 (hi,lo), K-major rows.
// Tile 128x128, BK=32, 2-stage cp.async, 8 warps (4m x 2n), m16n8k16 HMMA.
#define ROWB 80            // padded row stride in bytes (40 bf16)
#define ARRB 10240         // bytes per array per stage (128 * 80)
#define STGB 40960         // bytes per stage (4 arrays)
#define GSMEM (2 * STGB)   // 81920

__device__ __forceinline__ void load_stage(
    uint32_t s0, int tid, int bm, int bn, int kc, int K,
    const __nv_bfloat16* __restrict__ Ah, const __nv_bfloat16* __restrict__ Al,
    const __nv_bfloat16* __restrict__ Bh, const __nv_bfloat16* __restrict__ Bl) {
    #pragma unroll
    for (int i = 0; i < 8; i++) {
        int t = tid + i * 256;
        int arr = t >> 9, c = t & 511, row = c >> 2, ch = c & 3;
        const __nv_bfloat16* base = (arr == 0) ? Ah : (arr == 1) ? Al : (arr == 2) ? Bh : Bl;
        int grow = ((arr < 2) ? bm : bn) + row;
        cp16(s0 + arr * ARRB + row * ROWB + ch * 16,
             base + (size_t)grow * K + kc + ch * 8);
    }
    cp_commit();
}

__device__ __forceinline__ void compute_stage(uint32_t s0, int wm, int wn, int lane,
                                              float (&acc)[2][8][4]) {
    uint32_t ldrow = lane & 15;
    uint32_t ldcol = (lane >> 4) * 16;  // byte offset of 8-elem group
    #pragma unroll
    for (int kk = 0; kk < 2; kk++) {
        uint32_t kbyte = kk * 32 + ldcol;
        uint32_t ah[2][4], al[2][4];
        #pragma unroll
        for (int mi = 0; mi < 2; mi++) {
            uint32_t r = wm * 32 + mi * 16 + ldrow;
            ldm_x4(ah[mi], s0 + 0    + r * ROWB + kbyte);
            ldm_x4(al[mi], s0 + ARRB + r * ROWB + kbyte);
        }
        #pragma unroll
        for (int g = 0; g < 4; g++) {
            uint32_t r = wn * 64 + g * 16 + ldrow;
            uint32_t bh4[4], bl4[4];
            ldm_x4(bh4, s0 + 2 * ARRB + r * ROWB + kbyte);
            ldm_x4(bl4, s0 + 3 * ARRB + r * ROWB + kbyte);
            uint32_t b0h[2] = {bh4[0], bh4[2]}, b1h[2] = {bh4[1], bh4[3]};
            uint32_t b0l[2] = {bl4[0], bl4[2]}, b1l[2] = {bl4[1], bl4[3]};
            #pragma unroll
            for (int mi = 0; mi < 2; mi++) {
                mma16816(acc[mi][2 * g],     ah[mi], b0h);
                mma16816(acc[mi][2 * g + 1], ah[mi], b1h);
                mma16816(acc[mi][2 * g],     ah[mi], b0l);
                mma16816(acc[mi][2 * g + 1], ah[mi], b1l);
                mma16816(acc[mi][2 * g],     al[mi], b0h);
                mma16816(acc[mi][2 * g + 1], al[mi], b1h);
            }
        }
    }
}

__global__ void __launch_bounds__(256, 2) gemm_mma(
    const __nv_bfloat16* __restrict__ Ah, const __nv_bfloat16* __restrict__ Al,
    const __nv_bfloat16* __restrict__ Bh, const __nv_bfloat16* __restrict__ Bl,
    const float* __restrict__ bias,
    float* __restrict__ Cf,
    __nv_bfloat16* __restrict__ Chi, __nv_bfloat16* __restrict__ Clo,
    int M, int N, int K, int act) {
    extern __shared__ char smem[];
    uint32_t sb = smem_u32(smem);
    int tid = threadIdx.x, lane = tid & 31, wid = tid >> 5;
    int wm = wid & 3, wn = wid >> 2;
    int bm = blockIdx.y * 128, bn = blockIdx.x * 128;

    float acc[2][8][4];
    #pragma unroll
    for (int a = 0; a < 2; a++)
        #pragma unroll
        for (int b = 0; b < 8; b++)
            #pragma unroll
            for (int c = 0; c < 4; c++) acc[a][b][c] = 0.0f;

    const int NC = K / 32;
    load_stage(sb, tid, bm, bn, 0, K, Ah, Al, Bh, Bl);

    for (int c = 0; c < NC; c++) {
        if (c + 1 < NC) {
            load_stage(sb + ((c + 1) & 1) * STGB, tid, bm, bn, (c + 1) * 32, K,
                       Ah, Al, Bh, Bl);
            cp_wait1();
        } else {
            cp_wait0();
        }
        __syncthreads();
        compute_stage(sb + (c & 1) * STGB, wm, wn, lane, acc);
        __syncthreads();
    }

    // epilogue
    int tr = lane >> 2, tc = (lane & 3) * 2;
    #pragma unroll
    for (int mi = 0; mi < 2; mi++) {
        #pragma unroll
        for (int hr = 0; hr < 2; hr++) {
            int m = bm + wm * 32 + mi * 16 + hr * 8 + tr;
            #pragma unroll
            for (int ni = 0; ni < 8; ni++) {
                int n = bn + wn * 64 + ni * 8 + tc;
                float v0 = acc[mi][ni][hr * 2]     + bias[n];
                float v1 = acc[mi][ni][hr * 2 + 1] + bias[n + 1];
                if (act) {
                    v0 = 0.5f * v0 * (1.0f + erff(v0 * 0.70710678118654752f));
                    v1 = 0.5f * v1 * (1.0f + erff(v1 * 0.70710678118654752f));
                }
                if (Cf)
                    *(float2*)(Cf + (size_t)m * N + n) = make_float2(v0, v1);
                if (Chi) {
                    __nv_bfloat16 h0, l0, h1, l1;
                    split2(v0, h0, l0);
                    split2(v1, h1, l1);
                    uint32_t ph = (uint32_t)__bfloat16_as_ushort(h0) |
                                  ((uint32_t)__bfloat16_as_ushort(h1) << 16);
                    uint32_t pl = (uint32_t)__bfloat16_as_ushort(l0) |
                                  ((uint32_t)__bfloat16_as_ushort(l1) << 16);
                    *(uint32_t*)(Chi + (size_t)m * N + n) = ph;
                    *(uint32_t*)(Clo + (size_t)m * N + n) = pl;
                }
            }
        }
    }
}

// ---------------- Attention: one block per (b, head); K/V resident in smem ----------------
__global__ void attention_kernel(const float* __restrict__ qkv,
                                 const int* __restrict__ mask,
                                 __nv_bfloat16* __restrict__ Oh,
                                 __nv_bfloat16* __restrict__ Ol) {
    extern __shared__ float sm[];
    float* Ks    = sm;                   // 256 * 68
    float* Vs    = Ks + 256 * 68;        // 256 * 68
    float* qs    = Vs + 256 * 68;        // 8 * 68
    float* biasv = qs + 8 * 68;          // 256
    float* probs = biasv + 256;          // 8 * 256

    int bh = blockIdx.x;
    int b = bh / NH_, h = bh % NH_;
    int tid = threadIdx.x, lane = tid & 31, w = tid >> 5;
    const size_t qbase = ((size_t)b * S_) * QS_ + (size_t)h * HD_;

    for (int idx = tid; idx < 256 * 16; idx += 256) {
        int row = idx >> 4, c4 = idx & 15;
        float4 kv = *(const float4*)(qkv + qbase + (size_t)row * QS_ + H_ + c4 * 4);
        float4 vv = *(const float4*)(qkv + qbase + (size_t)row * QS_ + 2 * H_ + c4 * 4);
        *(float4*)(Ks + row * 68 + c4 * 4) = kv;
        *(float4*)(Vs + row * 68 + c4 * 4) = vv;
    }
    biasv[tid] = (1.0f - (float)mask[b * S_ + tid]) * -10000.0f;
    __syncthreads();

    const float scale = 0.125f;  // 1/sqrt(64)
    const size_t obase = ((size_t)b * S_) * H_ + (size_t)h * HD_;
    for (int r = w; r < S_; r += 8) {
        __syncwarp();
        if (lane < 16)
            *(float4*)(qs + w * 68 + lane * 4) =
                *(const float4*)(qkv + qbase + (size_t)r * QS_ + lane * 4);
        __syncwarp();

        float sc[8];
        #pragma unroll
        for (int t = 0; t < 8; t++) {
            int j = t * 32 + lane;
            float a = 0.0f;
            #pragma unroll
            for (int d4 = 0; d4 < 16; d4++) {
                float4 kq = *(float4*)(Ks + j * 68 + d4 * 4);
                float4 qq = *(float4*)(qs + w * 68 + d4 * 4);
                a = fmaf(kq.x, qq.x, fmaf(kq.y, qq.y, fmaf(kq.z, qq.z, fmaf(kq.w, qq.w, a))));
            }
            sc[t] = a * scale + biasv[j];
        }
        float mx = sc[0];
        #pragma unroll
        for (int t = 1; t < 8; t++) mx = fmaxf(mx, sc[t]);
        #pragma unroll
        for (int o = 16; o; o >>= 1) mx = fmaxf(mx, __shfl_xor_sync(0xffffffffu, mx, o));
        float sum = 0.0f;
        #pragma unroll
        for (int t = 0; t < 8; t++) { sc[t] = __expf(sc[t] - mx); sum += sc[t]; }
        #pragma unroll
        for (int o = 16; o; o >>= 1) sum += __shfl_xor_sync(0xffffffffu, sum, o);
        float inv = 1.0f / sum;
        #pragma unroll
        for (int t = 0; t < 8; t++) probs[w * 256 + t * 32 + lane] = sc[t] * inv;
        __syncwarp();

        float a0 = 0.0f, a1 = 0.0f;
        for (int j = 0; j < 256; j++) {
            float p = probs[w * 256 + j];
            a0 = fmaf(p, Vs[j * 68 + lane], a0);
            a1 = fmaf(p, Vs[j * 68 + 32 + lane], a1);
        }
        size_t o0 = obase + (size_t)r * H_ + lane;
        size_t o1 = o0 + 32;
        __nv_bfloat16 hh, ll;
        split2(a0, hh, ll); Oh[o0] = hh; Ol[o0] = ll;
        split2(a1, hh, ll); Oh[o1] = hh; Ol[o1] = ll;
    }
}

// ---------------- Classification head ----------------
__global__ void head_kernel(const float* __restrict__ h,
                            const int* __restrict__ ann,
                            const float* __restrict__ hw,
                            const float* __restrict__ hb,
                            float* __restrict__ out) {
    __shared__ float red[32];
    int b = blockIdx.x;
    int tid = threadIdx.x;
    int a = ann[b];
    const float* cls = h + (size_t)b * S_ * H_;
    const float* w = hw + (size_t)a * H_ * NL_;
    float a0 = 0.0f, a1 = 0.0f;
    for (int i = tid; i < H_; i += 256) {
        float c = cls[i];
        a0 = fmaf(c, w[i * NL_ + 0], a0);
        a1 = fmaf(c, w[i * NL_ + 1], a1);
    }
    a0 = block_sum(a0, red);
    a1 = block_sum(a1, red);
    if (tid == 0) {
        out[b * NL_ + 0] = a0 + hb[a * NL_ + 0];
        out[b * NL_ + 1] = a1 + hb[a * NL_ + 1];
    }
}

// ---------------- Host launcher ----------------
extern "C" void kernel_launch(void* const* d_in, const int* in_sizes, int n_in,
                              void* d_out, int out_size) {
    (void)in_sizes; (void)n_in; (void)out_size;
    const int*   ids   = (const int*)  d_in[0];
    const int*   amask = (const int*)  d_in[1];
    const int*   tt    = (const int*)  d_in[2];
    const int*   ann   = (const int*)  d_in[3];
    const float* we    = (const float*)d_in[4];
    const float* pe    = (const float*)d_in[5];
    const float* te    = (const float*)d_in[6];
    const float* elns  = (const float*)d_in[7];
    const float* elnb  = (const float*)d_in[8];
    const float* Wq    = (const float*)d_in[9];
    const float* bq    = (const float*)d_in[10];
    const float* Wk    = (const float*)d_in[11];
    const float* bk    = (const float*)d_in[12];
    const float* Wv    = (const float*)d_in[13];
    const float* bv    = (const float*)d_in[14];
    const float* Wo    = (const float*)d_in[15];
    const float* bo    = (const float*)d_in[16];
    const float* l1s   = (const float*)d_in[17];
    const float* l1b   = (const float*)d_in[18];
    const float* W1    = (const float*)d_in[19];
    const float* b1    = (const float*)d_in[20];
    const float* W2    = (const float*)d_in[21];
    const float* b2    = (const float*)d_in[22];
    const float* l2s   = (const float*)d_in[23];
    const float* l2b   = (const float*)d_in[24];
    const float* hw    = (const float*)d_in[25];
    const float* hb    = (const float*)d_in[26];
    float* out = (float*)d_out;

    float *h, *tmp, *qkv, *bqkv;
    __nv_bfloat16 *hh, *hl, *ch, *cl, *fh, *fl;
    __nv_bfloat16 *wqkvh, *wqkvl, *woh, *wol, *w1h, *w1l, *w2h, *w2l;
    cudaGetSymbolAddress((void**)&h,    g_h);
    cudaGetSymbolAddress((void**)&tmp,  g_tmp);
    cudaGetSymbolAddress((void**)&qkv,  g_qkv);
    cudaGetSymbolAddress((void**)&bqkv, g_bqkv);
    cudaGetSymbolAddress((void**)&hh,   g_hh);
    cudaGetSymbolAddress((void**)&hl,   g_hl);
    cudaGetSymbolAddress((void**)&ch,   g_ch);
    cudaGetSymbolAddress((void**)&cl,   g_cl);
    cudaGetSymbolAddress((void**)&fh,   g_fh);
    cudaGetSymbolAddress((void**)&fl,   g_fl);
    cudaGetSymbolAddress((void**)&wqkvh, g_Wqkvh);
    cudaGetSymbolAddress((void**)&wqkvl, g_Wqkvl);
    cudaGetSymbolAddress((void**)&woh,  g_Woh);
    cudaGetSymbolAddress((void**)&wol,  g_Wol);
    cudaGetSymbolAddress((void**)&w1h,  g_W1h);
    cudaGetSymbolAddress((void**)&w1l,  g_W1l);
    cudaGetSymbolAddress((void**)&w2h,  g_W2h);
    cudaGetSymbolAddress((void**)&w2l,  g_W2l);

    const int asmem = (256 * 68 * 2 + 8 * 68 + 256 + 8 * 256) * 4;
    cudaFuncSetAttribute(attention_kernel,
                         cudaFuncAttributeMaxDynamicSharedMemorySize, asmem);
    cudaFuncSetAttribute(gemm_mma,
                         cudaFuncAttributeMaxDynamicSharedMemorySize, GSMEM);

    // weight prep
    dim3 pb(32, 8);
    prep_w_kernel<<<dim3(H_ / 32, H_ / 32, L_), pb>>>(Wq, wqkvh, wqkvl, H_, H_, QS_, 0);
    prep_w_kernel<<<dim3(H_ / 32, H_ / 32, L_), pb>>>(Wk, wqkvh, wqkvl, H_, H_, QS_, H_);
    prep_w_kernel<<<dim3(H_ / 32, H_ / 32, L_), pb>>>(Wv, wqkvh, wqkvl, H_, H_, QS_, 2 * H_);
    prep_w_kernel<<<dim3(H_ / 32, H_ / 32, L_), pb>>>(Wo, woh, wol, H_, H_, H_, 0);
    prep_w_kernel<<<dim3(FF_ / 32, H_ / 32, L_), pb>>>(W1, w1h, w1l, H_, FF_, FF_, 0);
    prep_w_kernel<<<dim3(H_ / 32, FF_ / 32, L_), pb>>>(W2, w2h, w2l, FF_, H_, H_, 0);
    concat_bias_kernel<<<(L_ * QS_ + 255) / 256, 256>>>(bq, bk, bv, bqkv);

    embed_ln_kernel<<<NTOK, 256>>>(ids, tt, we, pe, te, elns, elnb, h, hh, hl);

    dim3 gQKV(QS_ / 128, NTOK / 128);  // (18, 128)
    dim3 gH  (H_  / 128, NTOK / 128);  // (6, 128)
    dim3 gFF (FF_ / 128, NTOK / 128);  // (24, 128)

    for (int l = 0; l < L_; l++) {
        size_t wqo = (size_t)l * QS_ * H_;
        size_t woo = (size_t)l * H_ * H_;
        size_t wfo = (size_t)l * H_ * FF_;

        gemm_mma<<<gQKV, 256, GSMEM>>>(hh, hl, wqkvh + wqo, wqkvl + wqo,
                                       bqkv + (size_t)l * QS_,
                                       qkv, nullptr, nullptr, NTOK, QS_, H_, 0);

        attention_kernel<<<B_ * NH_, 256, asmem>>>(qkv, amask, ch, cl);

        gemm_mma<<<gH, 256, GSMEM>>>(ch, cl, woh + woo, wol + woo,
                                     bo + (size_t)l * H_,
                                     tmp, nullptr, nullptr, NTOK, H_, H_, 0);
        add_ln_kernel<<<NTOK, 256>>>(h, tmp, l1s + (size_t)l * H_, l1b + (size_t)l * H_, hh, hl);

        gemm_mma<<<gFF, 256, GSMEM>>>(hh, hl, w1h + wfo, w1l + wfo,
                                      b1 + (size_t)l * FF_,
                                      nullptr, fh, fl, NTOK, FF_, H_, 1);
        gemm_mma<<<gH, 256, GSMEM>>>(fh, fl, w2h + wfo, w2l + wfo,
                                     b2 + (size_t)l * H_,
                                     tmp, nullptr, nullptr, NTOK, H_, FF_, 0);
        add_ln_kernel<<<NTOK, 256>>>(h, tmp, l2s + (size_t)l * H_, l2b + (size_t)l * H_, hh, hl);
    }

    head_kernel<<<B_, 256>>>(h, ann, hw, hb, out);
}

// round 4
// speedup vs baseline: 2.5748x; 1.2610x over previous
#include <cuda_runtime.h>
#include <cuda_fp16.h>
#include <math.h>
#include <cstdint>

// ---------------- Problem constants ----------------
#define B_  64
#define S_  256
#define H_  768
#define L_  12
#define NH_ 12
#define HD_ 64
#define FF_ 3072
#define NTOK (B_ * S_)          // 16384
#define NL_ 2
#define QS_ 2304                // fused qkv row stride

// ---------------- Scratch (static device globals; no allocation) ----------------
__device__ float g_h  [NTOK * H_];
__device__ float g_tmp[NTOK * H_];
__device__ float g_qkv[(size_t)NTOK * QS_];

__device__ __half g_hh[NTOK * H_];
__device__ __half g_hl[NTOK * H_];
__device__ __half g_ch[NTOK * H_];
__device__ __half g_cl[NTOK * H_];
__device__ __half g_fh[(size_t)NTOK * FF_];
__device__ __half g_fl[(size_t)NTOK * FF_];

// transposed weights: [L][N][K] (K-major rows), single fp16
__device__ __half g_Wqkv[(size_t)L_ * QS_ * H_];
__device__ __half g_Wo  [(size_t)L_ * H_ * H_];
__device__ __half g_W1  [(size_t)L_ * H_ * FF_];
__device__ __half g_W2  [(size_t)L_ * FF_ * H_];
__device__ float  g_bqkv[L_ * QS_];

// ---------------- low-level helpers ----------------
__device__ __forceinline__ uint32_t smem_u32(const void* p) {
    uint32_t a;
    asm("{ .reg .u64 t; cvta.to.shared.u64 t, %1; cvt.u32.u64 %0, t; }" : "=r"(a) : "l"(p));
    return a;
}
__device__ __forceinline__ void cp16(uint32_t dst, const void* src) {
    asm volatile("cp.async.cg.shared.global [%0], [%1], 16;" :: "r"(dst), "l"(src) : "memory");
}
__device__ __forceinline__ void cp_commit() { asm volatile("cp.async.commit_group;" ::: "memory"); }
__device__ __forceinline__ void cp_wait0()  { asm volatile("cp.async.wait_group 0;" ::: "memory"); }
__device__ __forceinline__ void cp_wait1()  { asm volatile("cp.async.wait_group 1;" ::: "memory"); }

__device__ __forceinline__ void ldm_x4(uint32_t* r, uint32_t addr) {
    asm volatile("ldmatrix.sync.aligned.m8n8.x4.shared.b16 {%0,%1,%2,%3}, [%4];"
                 : "=r"(r[0]), "=r"(r[1]), "=r"(r[2]), "=r"(r[3]) : "r"(addr));
}
__device__ __forceinline__ void mma16816(float* d, const uint32_t* a, const uint32_t* b) {
    asm volatile("mma.sync.aligned.m16n8k16.row.col.f32.f16.f16.f32 "
                 "{%0,%1,%2,%3}, {%4,%5,%6,%7}, {%8,%9}, {%0,%1,%2,%3};"
                 : "+f"(d[0]), "+f"(d[1]), "+f"(d[2]), "+f"(d[3])
                 : "r"(a[0]), "r"(a[1]), "r"(a[2]), "r"(a[3]), "r"(b[0]), "r"(b[1]));
}

__device__ __forceinline__ void split2h(float v, __half& h, __half& l) {
    h = __float2half_rn(v);
    l = __float2half_rn(v - __half2float(h));
}

// ---------------- Block reduction helper ----------------
__device__ __forceinline__ float block_sum(float v, float* red) {
    #pragma unroll
    for (int o = 16; o; o >>= 1) v += __shfl_xor_sync(0xffffffffu, v, o);
    int w = threadIdx.x >> 5, l = threadIdx.x & 31;
    if (l == 0) red[w] = v;
    __syncthreads();
    if (w == 0) {
        v = (l < (int)(blockDim.x >> 5)) ? red[l] : 0.0f;
        #pragma unroll
        for (int o = 16; o; o >>= 1) v += __shfl_xor_sync(0xffffffffu, v, o);
        if (l == 0) red[0] = v;
    }
    __syncthreads();
    float r = red[0];
    __syncthreads();
    return r;
}

// ---------------- Weight prep: W[L][K][N] fp32 -> Wd [L][Ntot][K] fp16 (rows noff..) -------
__global__ void prep_w_kernel(const float* __restrict__ W,
                              __half* __restrict__ Wd,
                              int K, int N, int Ntot, int noff) {
    __shared__ float t[32][33];
    int l  = blockIdx.z;
    int k0 = blockIdx.y * 32, n0 = blockIdx.x * 32;
    const float* Wp = W + (size_t)l * K * N;
    for (int r = threadIdx.y; r < 32; r += 8)
        t[r][threadIdx.x] = Wp[(size_t)(k0 + r) * N + n0 + threadIdx.x];
    __syncthreads();
    for (int r = threadIdx.y; r < 32; r += 8) {
        int n = n0 + r, k = k0 + threadIdx.x;
        size_t o = (size_t)l * Ntot * K + (size_t)(noff + n) * K + k;
        Wd[o] = __float2half_rn(t[threadIdx.x][r]);
    }
}

__global__ void concat_bias_kernel(const float* __restrict__ bq,
                                   const float* __restrict__ bk,
                                   const float* __restrict__ bv,
                                   float* __restrict__ dst) {
    int i = blockIdx.x * 256 + threadIdx.x;
    if (i >= L_ * QS_) return;
    int l = i / QS_, n = i % QS_;
    float v = (n < H_) ? bq[l * H_ + n]
            : (n < 2 * H_) ? bk[l * H_ + n - H_]
            : bv[l * H_ + n - 2 * H_];
    dst[i] = v;
}

// ---------------- Embedding + LayerNorm (+ fp16 hi/lo split) ----------------
__global__ void embed_ln_kernel(const int* __restrict__ ids,
                                const int* __restrict__ tt,
                                const float* __restrict__ we,
                                const float* __restrict__ pe,
                                const float* __restrict__ te,
                                const float* __restrict__ s,
                                const float* __restrict__ b,
                                float* __restrict__ out,
                                __half* __restrict__ oh,
                                __half* __restrict__ ol) {
    __shared__ float red[32];
    int tok = blockIdx.x;
    int tid = threadIdx.x;
    int srow = tok % S_;
    int id = ids[tok];
    int t  = tt[tok];
    float x[3];
    #pragma unroll
    for (int r = 0; r < 3; r++) {
        int i = tid + 256 * r;
        x[r] = we[(size_t)id * H_ + i] + pe[(size_t)srow * H_ + i] + te[(size_t)t * H_ + i];
    }
    float sum = block_sum(x[0] + x[1] + x[2], red);
    float m = sum * (1.0f / H_);
    float vs = 0.0f;
    #pragma unroll
    for (int r = 0; r < 3; r++) { float d = x[r] - m; vs += d * d; }
    vs = block_sum(vs, red);
    float inv = rsqrtf(vs * (1.0f / H_) + 1e-12f);
    #pragma unroll
    for (int r = 0; r < 3; r++) {
        int i = tid + 256 * r;
        float vv = (x[r] - m) * inv * s[i] + b[i];
        size_t o = (size_t)tok * H_ + i;
        out[o] = vv;
        __half hh, ll; split2h(vv, hh, ll);
        oh[o] = hh; ol[o] = ll;
    }
}

// ---------------- Residual add + LayerNorm (in place) + fp16 hi/lo ----------------
__global__ void add_ln_kernel(float* __restrict__ h,
                              const float* __restrict__ t,
                              const float* __restrict__ s,
                              const float* __restrict__ b,
                              __half* __restrict__ oh,
                              __half* __restrict__ ol) {
    __shared__ float red[32];
    int tok = blockIdx.x;
    int tid = threadIdx.x;
    float x[3];
    #pragma unroll
    for (int r = 0; r < 3; r++) {
        int i = tid + 256 * r;
        x[r] = h[(size_t)tok * H_ + i] + t[(size_t)tok * H_ + i];
    }
    float sum = block_sum(x[0] + x[1] + x[2], red);
    float m = sum * (1.0f / H_);
    float vs = 0.0f;
    #pragma unroll
    for (int r = 0; r < 3; r++) { float d = x[r] - m; vs += d * d; }
    vs = block_sum(vs, red);
    float inv = rsqrtf(vs * (1.0f / H_) + 1e-12f);
    #pragma unroll
    for (int r = 0; r < 3; r++) {
        int i = tid + 256 * r;
        float vv = (x[r] - m) * inv * s[i] + b[i];
        size_t o = (size_t)tok * H_ + i;
        h[o] = vv;
        __half hh, ll; split2h(vv, hh, ll);
        oh[o] = hh; ol[o] = ll;
    }
}

// ---------------- mma.sync GEMM with fp16x2 fp32 emulation ----------------
// C[M,N] = (Ah+Al)[M,K] @ W[N,K]^T + bias ; A hi/lo fp16, W single fp16, K-major.
// Tile 128x128, BK=32, 3-stage cp.async, 8 warps (4m x 2n), m16n8k16 HMMA.
#define ROWB 80            // padded row stride in bytes (32 fp16 = 64B + 16 pad)
#define ARRB 10240         // bytes per array per stage (128 * 80)
#define STGB 30720         // bytes per stage (3 arrays)
#define GSMEM (3 * STGB)   // 92160

__device__ __forceinline__ void load_stage(
    uint32_t s0, int tid, int bm, int bn, int kc, int K,
    const __half* __restrict__ Ah, const __half* __restrict__ Al,
    const __half* __restrict__ W) {
    #pragma unroll
    for (int i = 0; i < 6; i++) {
        int t = tid + i * 256;                 // 0..1535
        int arr = t >> 9, c = t & 511, row = c >> 2, ch = c & 3;
        const __half* base = (arr == 0) ? Ah : (arr == 1) ? Al : W;
        int grow = ((arr < 2) ? bm : bn) + row;
        cp16(s0 + arr * ARRB + row * ROWB + ch * 16,
             base + (size_t)grow * K + kc + ch * 8);
    }
    cp_commit();
}

__device__ __forceinline__ void compute_stage(uint32_t s0, int wm, int wn, int lane,
                                              float (&acc)[2][8][4]) {
    uint32_t ldrow = lane & 15;
    uint32_t ldcol = (lane >> 4) * 16;
    #pragma unroll
    for (int kk = 0; kk < 2; kk++) {
        uint32_t kbyte = kk * 32 + ldcol;
        uint32_t ah[2][4], al[2][4];
        #pragma unroll
        for (int mi = 0; mi < 2; mi++) {
            uint32_t r = wm * 32 + mi * 16 + ldrow;
            ldm_x4(ah[mi], s0 + 0    + r * ROWB + kbyte);
            ldm_x4(al[mi], s0 + ARRB + r * ROWB + kbyte);
        }
        #pragma unroll
        for (int g = 0; g < 4; g++) {
            uint32_t r = wn * 64 + g * 16 + ldrow;
            uint32_t w4[4];
            ldm_x4(w4, s0 + 2 * ARRB + r * ROWB + kbyte);
            uint32_t b0[2] = {w4[0], w4[2]}, b1[2] = {w4[1], w4[3]};
            #pragma unroll
            for (int mi = 0; mi < 2; mi++) {
                mma16816(acc[mi][2 * g],     ah[mi], b0);
                mma16816(acc[mi][2 * g + 1], ah[mi], b1);
                mma16816(acc[mi][2 * g],     al[mi], b0);
                mma16816(acc[mi][2 * g + 1], al[mi], b1);
            }
        }
    }
}

__global__ void __launch_bounds__(256, 2) gemm_mma(
    const __half* __restrict__ Ah, const __half* __restrict__ Al,
    const __half* __restrict__ W,
    const float* __restrict__ bias,
    float* __restrict__ Cf,
    __half* __restrict__ Chi, __half* __restrict__ Clo,
    int M, int N, int K, int act) {
    extern __shared__ char smem[];
    uint32_t sb = smem_u32(smem);
    int tid = threadIdx.x, lane = tid & 31, wid = tid >> 5;
    int wm = wid & 3, wn = wid >> 2;
    int bm = blockIdx.y * 128, bn = blockIdx.x * 128;

    float acc[2][8][4];
    #pragma unroll
    for (int a = 0; a < 2; a++)
        #pragma unroll
        for (int b = 0; b < 8; b++)
            #pragma unroll
            for (int c = 0; c < 4; c++) acc[a][b][c] = 0.0f;

    const int NC = K / 32;
    load_stage(sb + 0 * STGB, tid, bm, bn, 0,  K, Ah, Al, W);
    load_stage(sb + 1 * STGB, tid, bm, bn, 32, K, Ah, Al, W);

    for (int c = 0; c < NC; c++) {
        if (c + 2 < NC) cp_wait1(); else cp_wait0();
        __syncthreads();
        if (c + 2 < NC)
            load_stage(sb + ((c + 2) % 3) * STGB, tid, bm, bn, (c + 2) * 32, K,
                       Ah, Al, W);
        compute_stage(sb + (c % 3) * STGB, wm, wn, lane, acc);
    }

    // epilogue
    int tr = lane >> 2, tc = (lane & 3) * 2;
    #pragma unroll
    for (int mi = 0; mi < 2; mi++) {
        #pragma unroll
        for (int hr = 0; hr < 2; hr++) {
            int m = bm + wm * 32 + mi * 16 + hr * 8 + tr;
            #pragma unroll
            for (int ni = 0; ni < 8; ni++) {
                int n = bn + wn * 64 + ni * 8 + tc;
                float v0 = acc[mi][ni][hr * 2]     + bias[n];
                float v1 = acc[mi][ni][hr * 2 + 1] + bias[n + 1];
                if (act) {
                    v0 = 0.5f * v0 * (1.0f + erff(v0 * 0.70710678118654752f));
                    v1 = 0.5f * v1 * (1.0f + erff(v1 * 0.70710678118654752f));
                }
                if (Cf)
                    *(float2*)(Cf + (size_t)m * N + n) = make_float2(v0, v1);
                if (Chi) {
                    __half h0, l0, h1, l1;
                    split2h(v0, h0, l0);
                    split2h(v1, h1, l1);
                    uint32_t ph = (uint32_t)__half_as_ushort(h0) |
                                  ((uint32_t)__half_as_ushort(h1) << 16);
                    uint32_t pl = (uint32_t)__half_as_ushort(l0) |
                                  ((uint32_t)__half_as_ushort(l1) << 16);
                    *(uint32_t*)(Chi + (size_t)m * N + n) = ph;
                    *(uint32_t*)(Clo + (size_t)m * N + n) = pl;
                }
            }
        }
    }
}

// ---------------- Attention: one block per (b, head); K/V resident in smem ----------------
__global__ void attention_kernel(const float* __restrict__ qkv,
                                 const int* __restrict__ mask,
                                 __half* __restrict__ Oh,
                                 __half* __restrict__ Ol) {
    extern __shared__ float sm[];
    float* Ks    = sm;                   // 256 * 68
    float* Vs    = Ks + 256 * 68;        // 256 * 68
    float* qs    = Vs + 256 * 68;        // 8 * 68
    float* biasv = qs + 8 * 68;          // 256
    float* probs = biasv + 256;          // 8 * 256

    int bh = blockIdx.x;
    int b = bh / NH_, h = bh % NH_;
    int tid = threadIdx.x, lane = tid & 31, w = tid >> 5;
    const size_t qbase = ((size_t)b * S_) * QS_ + (size_t)h * HD_;

    for (int idx = tid; idx < 256 * 16; idx += 256) {
        int row = idx >> 4, c4 = idx & 15;
        float4 kv = *(const float4*)(qkv + qbase + (size_t)row * QS_ + H_ + c4 * 4);
        float4 vv = *(const float4*)(qkv + qbase + (size_t)row * QS_ + 2 * H_ + c4 * 4);
        *(float4*)(Ks + row * 68 + c4 * 4) = kv;
        *(float4*)(Vs + row * 68 + c4 * 4) = vv;
    }
    biasv[tid] = (1.0f - (float)mask[b * S_ + tid]) * -10000.0f;
    __syncthreads();

    const float scale = 0.125f;  // 1/sqrt(64)
    const size_t obase = ((size_t)b * S_) * H_ + (size_t)h * HD_;
    for (int r = w; r < S_; r += 8) {
        __syncwarp();
        if (lane < 16)
            *(float4*)(qs + w * 68 + lane * 4) =
                *(const float4*)(qkv + qbase + (size_t)r * QS_ + lane * 4);
        __syncwarp();

        float sc[8];
        #pragma unroll
        for (int t = 0; t < 8; t++) {
            int j = t * 32 + lane;
            float a = 0.0f;
            #pragma unroll
            for (int d4 = 0; d4 < 16; d4++) {
                float4 kq = *(float4*)(Ks + j * 68 + d4 * 4);
                float4 qq = *(float4*)(qs + w * 68 + d4 * 4);
                a = fmaf(kq.x, qq.x, fmaf(kq.y, qq.y, fmaf(kq.z, qq.z, fmaf(kq.w, qq.w, a))));
            }
            sc[t] = a * scale + biasv[j];
        }
        float mx = sc[0];
        #pragma unroll
        for (int t = 1; t < 8; t++) mx = fmaxf(mx, sc[t]);
        #pragma unroll
        for (int o = 16; o; o >>= 1) mx = fmaxf(mx, __shfl_xor_sync(0xffffffffu, mx, o));
        float sum = 0.0f;
        #pragma unroll
        for (int t = 0; t < 8; t++) { sc[t] = __expf(sc[t] - mx); sum += sc[t]; }
        #pragma unroll
        for (int o = 16; o; o >>= 1) sum += __shfl_xor_sync(0xffffffffu, sum, o);
        float inv = 1.0f / sum;
        #pragma unroll
        for (int t = 0; t < 8; t++) probs[w * 256 + t * 32 + lane] = sc[t] * inv;
        __syncwarp();

        float a0 = 0.0f, a1 = 0.0f;
        for (int j = 0; j < 256; j++) {
            float p = probs[w * 256 + j];
            a0 = fmaf(p, Vs[j * 68 + lane], a0);
            a1 = fmaf(p, Vs[j * 68 + 32 + lane], a1);
        }
        size_t o0 = obase + (size_t)r * H_ + lane;
        size_t o1 = o0 + 32;
        __half hh, ll;
        split2h(a0, hh, ll); Oh[o0] = hh; Ol[o0] = ll;
        split2h(a1, hh, ll); Oh[o1] = hh; Ol[o1] = ll;
    }
}

// ---------------- Classification head ----------------
__global__ void head_kernel(const float* __restrict__ h,
                            const int* __restrict__ ann,
                            const float* __restrict__ hw,
                            const float* __restrict__ hb,
                            float* __restrict__ out) {
    __shared__ float red[32];
    int b = blockIdx.x;
    int tid = threadIdx.x;
    int a = ann[b];
    const float* cls = h + (size_t)b * S_ * H_;
    const float* w = hw + (size_t)a * H_ * NL_;
    float a0 = 0.0f, a1 = 0.0f;
    for (int i = tid; i < H_; i += 256) {
        float c = cls[i];
        a0 = fmaf(c, w[i * NL_ + 0], a0);
        a1 = fmaf(c, w[i * NL_ + 1], a1);
    }
    a0 = block_sum(a0, red);
    a1 = block_sum(a1, red);
    if (tid == 0) {
        out[b * NL_ + 0] = a0 + hb[a * NL_ + 0];
        out[b * NL_ + 1] = a1 + hb[a * NL_ + 1];
    }
}

// ---------------- Host launcher ----------------
extern "C" void kernel_launch(void* const* d_in, const int* in_sizes, int n_in,
                              void* d_out, int out_size) {
    (void)in_sizes; (void)n_in; (void)out_size;
    const int*   ids   = (const int*)  d_in[0];
    const int*   amask = (const int*)  d_in[1];
    const int*   tt    = (const int*)  d_in[2];
    const int*   ann   = (const int*)  d_in[3];
    const float* we    = (const float*)d_in[4];
    const float* pe    = (const float*)d_in[5];
    const float* te    = (const float*)d_in[6];
    const float* elns  = (const float*)d_in[7];
    const float* elnb  = (const float*)d_in[8];
    const float* Wq    = (const float*)d_in[9];
    const float* bq    = (const float*)d_in[10];
    const float* Wk    = (const float*)d_in[11];
    const float* bk    = (const float*)d_in[12];
    const float* Wv    = (const float*)d_in[13];
    const float* bv    = (const float*)d_in[14];
    const float* Wo    = (const float*)d_in[15];
    const float* bo    = (const float*)d_in[16];
    const float* l1s   = (const float*)d_in[17];
    const float* l1b   = (const float*)d_in[18];
    const float* W1    = (const float*)d_in[19];
    const float* b1    = (const float*)d_in[20];
    const float* W2    = (const float*)d_in[21];
    const float* b2    = (const float*)d_in[22];
    const float* l2s   = (const float*)d_in[23];
    const float* l2b   = (const float*)d_in[24];
    const float* hw    = (const float*)d_in[25];
    const float* hb    = (const float*)d_in[26];
    float* out = (float*)d_out;

    float *h, *tmp, *qkv, *bqkv;
    __half *hh, *hl, *ch, *cl, *fh, *fl;
    __half *wqkv, *wo, *w1, *w2;
    cudaGetSymbolAddress((void**)&h,    g_h);
    cudaGetSymbolAddress((void**)&tmp,  g_tmp);
    cudaGetSymbolAddress((void**)&qkv,  g_qkv);
    cudaGetSymbolAddress((void**)&bqkv, g_bqkv);
    cudaGetSymbolAddress((void**)&hh,   g_hh);
    cudaGetSymbolAddress((void**)&hl,   g_hl);
    cudaGetSymbolAddress((void**)&ch,   g_ch);
    cudaGetSymbolAddress((void**)&cl,   g_cl);
    cudaGetSymbolAddress((void**)&fh,   g_fh);
    cudaGetSymbolAddress((void**)&fl,   g_fl);
    cudaGetSymbolAddress((void**)&wqkv, g_Wqkv);
    cudaGetSymbolAddress((void**)&wo,   g_Wo);
    cudaGetSymbolAddress((void**)&w1,   g_W1);
    cudaGetSymbolAddress((void**)&w2,   g_W2);

    const int asmem = (256 * 68 * 2 + 8 * 68 + 256 + 8 * 256) * 4;
    cudaFuncSetAttribute(attention_kernel,
                         cudaFuncAttributeMaxDynamicSharedMemorySize, asmem);
    cudaFuncSetAttribute(gemm_mma,
                         cudaFuncAttributeMaxDynamicSharedMemorySize, GSMEM);

    // weight prep
    dim3 pb(32, 8);
    prep_w_kernel<<<dim3(H_ / 32, H_ / 32, L_), pb>>>(Wq, wqkv, H_, H_, QS_, 0);
    prep_w_kernel<<<dim3(H_ / 32, H_ / 32, L_), pb>>>(Wk, wqkv, H_, H_, QS_, H_);
    prep_w_kernel<<<dim3(H_ / 32, H_ / 32, L_), pb>>>(Wv, wqkv, H_, H_, QS_, 2 * H_);
    prep_w_kernel<<<dim3(H_ / 32, H_ / 32, L_), pb>>>(Wo, wo, H_, H_, H_, 0);
    prep_w_kernel<<<dim3(FF_ / 32, H_ / 32, L_), pb>>>(W1, w1, H_, FF_, FF_, 0);
    prep_w_kernel<<<dim3(H_ / 32, FF_ / 32, L_), pb>>>(W2, w2, FF_, H_, H_, 0);
    concat_bias_kernel<<<(L_ * QS_ + 255) / 256, 256>>>(bq, bk, bv, bqkv);

    embed_ln_kernel<<<NTOK, 256>>>(ids, tt, we, pe, te, elns, elnb, h, hh, hl);

    dim3 gQKV(QS_ / 128, NTOK / 128);  // (18, 128)
    dim3 gH  (H_  / 128, NTOK / 128);  // (6, 128)
    dim3 gFF (FF_ / 128, NTOK / 128);  // (24, 128)

    for (int l = 0; l < L_; l++) {
        size_t wqo = (size_t)l * QS_ * H_;
        size_t woo = (size_t)l * H_ * H_;
        size_t wfo = (size_t)l * H_ * FF_;

        gemm_mma<<<gQKV, 256, GSMEM>>>(hh, hl, wqkv + wqo,
                                       bqkv + (size_t)l * QS_,
                                       qkv, nullptr, nullptr, NTOK, QS_, H_, 0);

        attention_kernel<<<B_ * NH_, 256, asmem>>>(qkv, amask, ch, cl);

        gemm_mma<<<gH, 256, GSMEM>>>(ch, cl, wo + woo,
                                     bo + (size_t)l * H_,
                                     tmp, nullptr, nullptr, NTOK, H_, H_, 0);
        add_ln_kernel<<<NTOK, 256>>>(h, tmp, l1s + (size_t)l * H_, l1b + (size_t)l * H_, hh, hl);

        gemm_mma<<<gFF, 256, GSMEM>>>(hh, hl, w1 + wfo,
                                      b1 + (size_t)l * FF_,
                                      nullptr, fh, fl, NTOK, FF_, H_, 1);
        gemm_mma<<<gH, 256, GSMEM>>>(fh, fl, w2 + wfo,
                                     b2 + (size_t)l * H_,
                                     tmp, nullptr, nullptr, NTOK, H_, FF_, 0);
        add_ln_kernel<<<NTOK, 256>>>(h, tmp, l2s + (size_t)l * H_, l2b + (size_t)l * H_, hh, hl);
    }

    head_kernel<<<B_, 256>>>(h, ann, hw, hb, out);
}